// round 10
// baseline (speedup 1.0000x reference)
#include <cuda_runtime.h>
#include <cstdint>

// AdditiveAttention: out[b,q,v] = softmax_k( sum_h w_v[h]*tanh(q~[b,q,h]+k~[b,k,h]) ) @ V
// B=4, Q=256, K=1024, IN=256, H=128, V=256.

typedef unsigned long long ull;

// Scratch (__device__ globals — no allocation allowed)
__device__ float g_wqt[256 * 128];            // W_q^T [in][h]
__device__ float g_wkt[256 * 128];            // W_k^T [in][h]
__device__ float g_qp[4 * 256 * 128];         // projected queries
__device__ float g_kp[4 * 1024 * 128];        // projected keys
__device__ float g_pacc[16 * 256 * 256];      // partial acc [b*4+kq][q][v]
__device__ float g_psum[16 * 256];            // partial exp-sums [b*4+kq][q]
__device__ unsigned int g_flag_t;             // transpose-done counter (self-reset)
__device__ unsigned int g_done_p;             // prep completion counter (self-reset)
__device__ unsigned int g_cnt[256];           // per-(b,qt) partial counters (self-reset)

__device__ __forceinline__ float tanh_apx(float x) {
    float y;
    asm("tanh.approx.f32 %0, %1;" : "=f"(y) : "f"(x));
    return y;
}

__device__ __forceinline__ void fma2(ull& d, ull a, ull b) {
    asm("fma.rn.f32x2 %0, %1, %2, %0;" : "+l"(d) : "l"(a), "l"(b));
}

__device__ __forceinline__ ull pack2(float x) {
    ull r;
    asm("mov.b64 %0, {%1, %1};" : "=l"(r) : "f"(x));
    return r;
}

__device__ __forceinline__ void ldgsts16(uint32_t saddr, const void* g) {
    asm volatile("cp.async.cg.shared.global [%0], [%1], 16;"
                 :: "r"(saddr), "l"(g));
}
__device__ __forceinline__ void cp_commit() {
    asm volatile("cp.async.commit_group;" ::: "memory");
}
__device__ __forceinline__ void cp_wait0() {
    asm volatile("cp.async.wait_group 0;" ::: "memory");
}

// ---------------------------------------------------------------------------
// K_prep: fused weight transpose + projections. 160 blocks x 256 threads.
//  Phase T (blocks 0-63): tiled transpose W -> g_wqt/g_wkt; bump g_flag_t.
//  All blocks spin on g_flag_t==64 (deadlock-free: 160 blocks all resident at
//  >=2 blocks/SM; producers are in the first wave), then project 32 rows each:
//  blocks [0,128): keys -> g_kp;  [128,160): queries -> g_qp.
//  X staged transposed as float2 row-pairs xs2[i*18+p] (pad 18 -> 2-way STS).
//  Wt streamed via cp.async double-buffered 32i x 128h tiles (coalesced).
//  Thread: 2 h (h2,h2+1) x 4 row-pairs -> 8 f32x2 accs; per i: 1 LDS.64 w +
//  2 pack + 4 LDS.64 x + 8 fma2 = 15 issues / 16 FMAs -> FMA-bound.
//  Counters self-reset by last finishing block.
// ---------------------------------------------------------------------------
#define SMEM_PREP (36864 + 32768)   // xs2 [256][18]f2 + wt [2][32*128]f

__global__ __launch_bounds__(256, 2) void k_prep(
    const float* __restrict__ queries, const float* __restrict__ keys,
    const float* __restrict__ Wq, const float* __restrict__ Wk) {
    extern __shared__ float psm[];
    float2* xs2 = (float2*)psm;          // [256][18] float2
    float*  wt  = psm + 9216;            // [2][4096] floats
    __shared__ float ttile[32][33];

    int bid = blockIdx.x;
    int t = threadIdx.x;

    // ---- Phase T: transpose (blocks 0-63) ----
    if (bid < 64) {
        int m = bid >> 5;
        int tb = bid & 31;
        int hb = tb >> 3, ib = tb & 7;
        const float* W = m ? Wk : Wq;
        float* Wt = m ? g_wkt : g_wqt;
        int c = t & 31, r0 = t >> 5;
        #pragma unroll
        for (int rr = 0; rr < 4; ++rr) {
            int r = r0 * 4 + rr;
            ttile[r][c] = W[(hb * 32 + r) * 256 + ib * 32 + c];
        }
        __syncthreads();
        #pragma unroll
        for (int rr = 0; rr < 4; ++rr) {
            int r = r0 * 4 + rr;
            Wt[(ib * 32 + r) * 128 + hb * 32 + c] = ttile[c][r];
        }
        __threadfence();
        __syncthreads();
        if (t == 0) atomicAdd(&g_flag_t, 1u);
    }

    // ---- spin until all 64 transpose blocks done ----
    if (t == 0) {
        while (atomicAdd(&g_flag_t, 0u) < 64u) {}
        __threadfence();
    }
    __syncthreads();

    // ---- Phase P: projection of 32 rows ----
    const float* src;
    const float* Wt;
    float* dst;
    int r0g;
    if (bid < 128) { src = keys;    Wt = g_wkt; dst = g_kp; r0g = bid * 32; }
    else           { src = queries; Wt = g_wqt; dst = g_qp; r0g = (bid - 128) * 32; }

    uint32_t wtaddr = (uint32_t)__cvta_generic_to_shared(wt);
    const float4* Wt4 = (const float4*)Wt;

    // issue Wt tile 0 (32 i x 128 h = 16 KB, contiguous)
    #pragma unroll
    for (int n = 0; n < 4; ++n) {
        int idx = t + n * 256;                        // 0..1023 float4
        ldgsts16(wtaddr + (uint32_t)(idx * 16), Wt4 + idx);
    }
    cp_commit();

    // stage X transposed into row-pair float2 layout (pad 18 -> 2-way STS)
    const float4* s4 = (const float4*)(src + r0g * 256);
    float* xsf = (float*)xs2;
    #pragma unroll 4
    for (int n = 0; n < 8; ++n) {
        int idx4 = t + n * 256;                       // 0..2047 float4
        int r = idx4 >> 6, i4 = idx4 & 63;
        float4 v = s4[idx4];
        xsf[(i4 * 4 + 0) * 36 + r] = v.x;
        xsf[(i4 * 4 + 1) * 36 + r] = v.y;
        xsf[(i4 * 4 + 2) * 36 + r] = v.z;
        xsf[(i4 * 4 + 3) * 36 + r] = v.w;
    }
    cp_wait0();

    int h2 = (t & 63) * 2;
    int rh = t >> 6;                     // 0..3 -> pairs rh*4..rh*4+3
    const float2* xp = xs2 + rh * 4;
    ull acc[4][2] = {{0ull,0ull},{0ull,0ull},{0ull,0ull},{0ull,0ull}};

    for (int tau = 0; tau < 8; ++tau) {
        __syncthreads();                 // tile tau + xs visible
        if (tau + 1 < 8) {
            int buf = (tau + 1) & 1;
            const float4* srcw = Wt4 + (tau + 1) * 1024;
            #pragma unroll
            for (int n = 0; n < 4; ++n) {
                int idx = t + n * 256;
                ldgsts16(wtaddr + (uint32_t)(buf * 16384 + idx * 16), srcw + idx);
            }
            cp_commit();
        }
        const float* wb = wt + (tau & 1) * 4096;
        #pragma unroll 8
        for (int ii = 0; ii < 32; ++ii) {
            float2 w2 = *(const float2*)&wb[ii * 128 + h2];
            ull wa = pack2(w2.x);
            ull wbp = pack2(w2.y);
            const float2* xi = xp + (tau * 32 + ii) * 18;
            ull x0 = *(const ull*)&xi[0];
            ull x1 = *(const ull*)&xi[1];
            ull x2 = *(const ull*)&xi[2];
            ull x3 = *(const ull*)&xi[3];
            fma2(acc[0][0], x0, wa); fma2(acc[0][1], x0, wbp);
            fma2(acc[1][0], x1, wa); fma2(acc[1][1], x1, wbp);
            fma2(acc[2][0], x2, wa); fma2(acc[2][1], x2, wbp);
            fma2(acc[3][0], x3, wa); fma2(acc[3][1], x3, wbp);
        }
        cp_wait0();
    }

    // write 8 rows x 2 h per thread as coalesced float2 (over h)
    #pragma unroll
    for (int p = 0; p < 4; ++p) {
        float2 A = *(float2*)&acc[p][0];   // h2   : {row even, row odd}
        float2 Bv = *(float2*)&acc[p][1];  // h2+1 : {row even, row odd}
        int r = r0g + rh * 8 + p * 2;
        float2 o0 = make_float2(A.x, Bv.x);
        float2 o1 = make_float2(A.y, Bv.y);
        *(float2*)&dst[r * 128 + h2] = o0;
        *(float2*)&dst[(r + 1) * 128 + h2] = o1;
    }

    // self-reset counters once every block finished
    __syncthreads();
    if (t == 0) {
        if (atomicAdd(&g_done_p, 1u) == 159u) {
            atomicExch(&g_flag_t, 0u);
            atomicExch(&g_done_p, 0u);
        }
    }
}

// ---------------------------------------------------------------------------
// K_attn5: split-K fused attn (as R9 k_attn4) + combine-on-last-arrival.
// 1024 blocks: b = bid&3, kq = (bid>>2)&3, qt = bid>>4; 4 q x 256 k / block,
// <=4 chunks of 64 k; blocks past vlen exit. ks double-buffered cp.async with
// rotation swizzle; mainloop fuses Phase A(c) with Phase C(c-1).
// After writing its partial, each block bumps g_cnt[b*64+qt]; the last of the
// np=ceil(vlen/256) participants reduces+normalizes rows q0..q0+3 into out
// and resets the counter. SMEM 72224 B -> 3 blocks/SM.
// ---------------------------------------------------------------------------
#define SMEM_ATTN (65536 + 2048 + 512 + 4096 + 32)

__global__ __launch_bounds__(256, 3) void k_attn5(
    const float* __restrict__ values, const int* __restrict__ valid_lens,
    const float* __restrict__ w_v, float* __restrict__ out) {
    extern __shared__ float sm[];
    float4* ks4  = (float4*)sm;                      // [2][64*32] float4
    float*  qs   = sm + 16384;                       // [4][128]
    float*  wvs  = qs + 512;                         // [128]
    float2* eb2  = (float2*)(wvs + 128);             // [2][256] = {e,e}
    float*  wsum = (float*)(eb2 + 512);              // [8]
    __shared__ unsigned int s_old;

    int bid = blockIdx.x;
    int b = bid & 3;
    int kq = (bid >> 2) & 3;
    int qt = bid >> 4;
    int vlen = valid_lens[b];
    int k0 = kq * 256;
    if (k0 >= vlen) return;
    int nch = min(4, (vlen - k0 + 63) >> 6);

    int t = threadIdx.x;
    int q0 = qt * 4;
    int qa = t >> 6;                 // warp-uniform q (0..3)
    int ka = t & 63;                 // A: key index within chunk
    int vp = (t & 63) * 4;           // C: 4 v-cols

    const float4* kp4 = (const float4*)(g_kp + (b * 1024 + k0) * 128);
    const float* Vb = values + (b * 1024 + k0) * 256;
    uint32_t ksaddr = (uint32_t)__cvta_generic_to_shared(ks4);

    // ---- issue chunk 0 copy ----
    #pragma unroll
    for (int n = 0; n < 8; ++n) {
        int idx = t + n * 256;                // 0..2047
        int kk = idx >> 5, h4 = idx & 31;
        uint32_t d = ksaddr + (uint32_t)((kk * 32 + ((h4 + kk) & 31)) * 16);
        ldgsts16(d, kp4 + kk * 32 + h4);
    }
    cp_commit();

    // ---- load qs, wvs while copy flies ----
    for (int i = t; i < 512; i += 256)
        qs[i] = g_qp[(b * 256 + q0) * 128 + i];
    if (t < 128) wvs[t] = w_v[t];
    cp_wait0();

    ull acc0 = 0ull, acc1 = 0ull;
    float lsum = 0.f;
    const float* qrow = qs + qa * 128;

    for (int c = 0; c < nch; ++c) {
        __syncthreads();   // chunk c copies + ebuf(c-1) visible

        if (c + 1 < nch) {
            int buf = (c + 1) & 1;
            const float4* srcc = kp4 + (c + 1) * 2048;
            #pragma unroll
            for (int n = 0; n < 8; ++n) {
                int idx = t + n * 256;
                int kk = idx >> 5, h4 = idx & 31;
                uint32_t d = ksaddr +
                    (uint32_t)((buf * 2048 + kk * 32 + ((h4 + kk) & 31)) * 16);
                ldgsts16(d, srcc + kk * 32 + h4);
            }
            cp_commit();
        }

        const float4* ksb = ks4 + (c & 1) * 2048 + ka * 32;
        float s = 0.f;

        if (c == 0) {
            #pragma unroll 8
            for (int j = 0; j < 32; ++j) {
                float4 kv = ksb[(j + ka) & 31];
                float4 q4 = *(const float4*)&qrow[j * 4];
                float4 w4 = *(const float4*)&wvs[j * 4];
                s = fmaf(w4.x, tanh_apx(q4.x + kv.x), s);
                s = fmaf(w4.y, tanh_apx(q4.y + kv.y), s);
                s = fmaf(w4.z, tanh_apx(q4.z + kv.z), s);
                s = fmaf(w4.w, tanh_apx(q4.w + kv.w), s);
            }
        } else {
            const float2* eb = eb2 + ((c & 1) ^ 1) * 256 + qa * 64;
            const float* Vp = Vb + (c - 1) * 64 * 256 + vp;
            #pragma unroll 4
            for (int j = 0; j < 32; ++j) {
                float4 kv = ksb[(j + ka) & 31];
                float4 q4 = *(const float4*)&qrow[j * 4];
                float4 w4 = *(const float4*)&wvs[j * 4];
                s = fmaf(w4.x, tanh_apx(q4.x + kv.x), s);
                s = fmaf(w4.y, tanh_apx(q4.y + kv.y), s);
                s = fmaf(w4.z, tanh_apx(q4.z + kv.z), s);
                s = fmaf(w4.w, tanh_apx(q4.w + kv.w), s);
                float2 e0 = eb[2 * j];
                float2 e1 = eb[2 * j + 1];
                float4 v0 = *(const float4*)&Vp[(2 * j) * 256];
                float4 v1 = *(const float4*)&Vp[(2 * j + 1) * 256];
                fma2(acc0, *(ull*)&e0, *(ull*)&v0.x);
                fma2(acc1, *(ull*)&e0, *(ull*)&v0.z);
                fma2(acc0, *(ull*)&e1, *(ull*)&v1.x);
                fma2(acc1, *(ull*)&e1, *(ull*)&v1.z);
            }
        }

        int kg = k0 + c * 64 + ka;
        float e = (kg < vlen) ? __expf(s) : 0.f;
        eb2[(c & 1) * 256 + qa * 64 + ka] = make_float2(e, e);
        lsum += e;
        if (c + 1 < nch) cp_wait0();
    }

    // ---- epilogue: C(nch-1) ----
    __syncthreads();
    {
        const float2* eb = eb2 + ((nch - 1) & 1) * 256 + qa * 64;
        const float* Vp = Vb + (nch - 1) * 64 * 256 + vp;
        #pragma unroll 4
        for (int kk = 0; kk < 64; ++kk) {
            float2 e0 = eb[kk];
            float4 v0 = *(const float4*)&Vp[kk * 256];
            fma2(acc0, *(ull*)&e0, *(ull*)&v0.x);
            fma2(acc1, *(ull*)&e0, *(ull*)&v0.z);
        }
    }

    // per-q exp sums: warps 2q, 2q+1 cover q
    lsum += __shfl_xor_sync(0xffffffffu, lsum, 16);
    lsum += __shfl_xor_sync(0xffffffffu, lsum, 8);
    lsum += __shfl_xor_sync(0xffffffffu, lsum, 4);
    lsum += __shfl_xor_sync(0xffffffffu, lsum, 2);
    lsum += __shfl_xor_sync(0xffffffffu, lsum, 1);
    int lane = t & 31, w = t >> 5;
    if (lane == 0) wsum[w] = lsum;
    __syncthreads();
    if (t < 4)
        g_psum[(b * 4 + kq) * 256 + q0 + t] = wsum[2 * t] + wsum[2 * t + 1];

    float* pa = &g_pacc[(((b * 4 + kq) * 256) + q0 + qa) * 256 + vp];
    float4 o;
    o.x = ((float2*)&acc0)->x; o.y = ((float2*)&acc0)->y;
    o.z = ((float2*)&acc1)->x; o.w = ((float2*)&acc1)->y;
    *(float4*)pa = o;

    // ---- combine-on-last-arrival ----
    __threadfence();
    __syncthreads();
    if (t == 0) s_old = atomicAdd(&g_cnt[b * 64 + qt], 1u);
    __syncthreads();

    int np = (vlen + 255) >> 8;           // participants for this (b, qt)
    if (s_old == (unsigned)(np - 1)) {
        __threadfence();                  // acquire: peers' partials visible
        #pragma unroll
        for (int qi = 0; qi < 4; ++qi) {
            int qq = q0 + qi;
            float a0 = g_pacc[((b * 4 + 0) * 256 + qq) * 256 + t];
            float s0 = g_psum[(b * 4 + 0) * 256 + qq];
            float a1 = (np > 1) ? g_pacc[((b * 4 + 1) * 256 + qq) * 256 + t] : 0.f;
            float s1 = (np > 1) ? g_psum[(b * 4 + 1) * 256 + qq] : 0.f;
            float a2 = (np > 2) ? g_pacc[((b * 4 + 2) * 256 + qq) * 256 + t] : 0.f;
            float s2 = (np > 2) ? g_psum[(b * 4 + 2) * 256 + qq] : 0.f;
            float a3 = (np > 3) ? g_pacc[((b * 4 + 3) * 256 + qq) * 256 + t] : 0.f;
            float s3 = (np > 3) ? g_psum[(b * 4 + 3) * 256 + qq] : 0.f;
            out[(b * 256 + qq) * 256 + t] =
                ((a0 + a1) + (a2 + a3)) / ((s0 + s1) + (s2 + s3));
        }
        if (t == 0) atomicExch(&g_cnt[b * 64 + qt], 0u);
    }
}

// ---------------------------------------------------------------------------
extern "C" void kernel_launch(void* const* d_in, const int* in_sizes, int n_in,
                              void* d_out, int out_size) {
    const float* queries    = (const float*)d_in[0];  // [4,256,256]
    const float* keys       = (const float*)d_in[1];  // [4,1024,256]
    const float* values     = (const float*)d_in[2];  // [4,1024,256]
    const int*   valid_lens = (const int*)d_in[3];    // [4]
    const float* W_q        = (const float*)d_in[4];  // [128,256]
    const float* W_k        = (const float*)d_in[5];  // [128,256]
    const float* w_v        = (const float*)d_in[6];  // [128]
    float* out = (float*)d_out;                       // [4,256,256]

    cudaFuncSetAttribute(k_prep, cudaFuncAttributeMaxDynamicSharedMemorySize,
                         SMEM_PREP);
    cudaFuncSetAttribute(k_attn5, cudaFuncAttributeMaxDynamicSharedMemorySize,
                         SMEM_ATTN);

    k_prep<<<160, 256, SMEM_PREP>>>(queries, keys, W_q, W_k);
    k_attn5<<<1024, 256, SMEM_ATTN>>>(values, valid_lens, w_v, out);
}